// round 1
// baseline (speedup 1.0000x reference)
#include <cuda_runtime.h>

#define Nn 100000
#define Gg 1000
#define Ee 1600000
#define EGe 16000

// ---------------- scratch (device globals; no runtime allocation) ----------------
static __device__ __align__(16) float g_h1[Nn*128];     // x @ W1
static __device__ __align__(16) float g_xout[Nn*128];   // GAT1 aggregation
static __device__ __align__(16) float g_asrc1[Nn*4];
static __device__ __align__(16) float g_adst1[Nn*4];
static __device__ __align__(16) float g_m1[Nn*4];
static __device__ __align__(16) float g_s1[Nn*4];
static __device__ __align__(16) float g_h2[Gg*128];
static __device__ __align__(16) float g_xg[Gg*128];     // GAT2 aggregation (pre-bias)
static __device__ __align__(16) float g_xgf[Gg*128];    // GAT2 final (with bias2)
static __device__ __align__(16) float g_adj[Gg*128];    // adjacent-group mean
static __device__ __align__(16) float g_asrc2[Gg*4];
static __device__ __align__(16) float g_adst2[Gg*4];
static __device__ __align__(16) float g_m2[Gg*4];
static __device__ __align__(16) float g_s2[Gg*4];
static __device__ float g_cnt[Gg];

__device__ __forceinline__ void atomicMaxF(float* addr, float v) {
    if (v >= 0.f) atomicMax((int*)addr, __float_as_int(v));
    else          atomicMin((unsigned int*)addr, __float_as_uint(v));
}

// ---------------- init ----------------
__global__ void init_kernel() {
    int i = blockIdx.x * blockDim.x + threadIdx.x;
    if (i < Nn*128) g_xout[i] = 0.f;
    if (i < Nn*4) { g_m1[i] = __int_as_float(0xff800000); g_s1[i] = 0.f; }
    if (i < Gg*128) { g_xg[i] = 0.f; g_adj[i] = 0.f; }
    if (i < Gg*4) { g_m2[i] = __int_as_float(0xff800000); g_s2[i] = 0.f; }
    if (i < Gg) g_cnt[i] = 0.f;
}

// ---------------- GEMM: C[n,128] = A[n,128] @ B[128,128] ----------------
// 256 threads, tile 64 rows x 128 cols, K-chunks of 16, 8x4 microtile/thread.
__global__ void gemm_k128(const float* __restrict__ A, const float* __restrict__ B,
                          int which, int n) {
    float* C = which ? g_h2 : g_h1;
    __shared__ float As[16][68];   // [k][row], padded
    __shared__ float Bs[16][128];  // [k][col]
    int t = threadIdx.x;
    int rowBase = blockIdx.x * 64;
    int tr = t >> 5, tc = t & 31;
    float acc[8][4];
    #pragma unroll
    for (int i = 0; i < 8; i++)
        #pragma unroll
        for (int j = 0; j < 4; j++) acc[i][j] = 0.f;

    for (int kt = 0; kt < 128; kt += 16) {
        int ar = t >> 2;
        int ac = (t & 3) << 2;
        int row = rowBase + ar;
        float4 av = (row < n) ? *(const float4*)(A + row*128 + kt + ac)
                              : make_float4(0.f, 0.f, 0.f, 0.f);
        As[ac+0][ar] = av.x; As[ac+1][ar] = av.y;
        As[ac+2][ar] = av.z; As[ac+3][ar] = av.w;
        int br = t >> 4;
        int bc = (t & 15) << 3;
        float4 b0 = *(const float4*)(B + (kt + br)*128 + bc);
        float4 b1 = *(const float4*)(B + (kt + br)*128 + bc + 4);
        *(float4*)&Bs[br][bc]     = b0;
        *(float4*)&Bs[br][bc + 4] = b1;
        __syncthreads();
        #pragma unroll
        for (int kk = 0; kk < 16; kk++) {
            float4 a0 = *(const float4*)&As[kk][tr*8];
            float4 a1 = *(const float4*)&As[kk][tr*8 + 4];
            float4 b  = *(const float4*)&Bs[kk][tc*4];
            float av_[8] = {a0.x,a0.y,a0.z,a0.w,a1.x,a1.y,a1.z,a1.w};
            #pragma unroll
            for (int i = 0; i < 8; i++) {
                acc[i][0] += av_[i]*b.x; acc[i][1] += av_[i]*b.y;
                acc[i][2] += av_[i]*b.z; acc[i][3] += av_[i]*b.w;
            }
        }
        __syncthreads();
    }
    #pragma unroll
    for (int i = 0; i < 8; i++) {
        int row = rowBase + tr*8 + i;
        if (row < n)
            *(float4*)(C + row*128 + tc*4) =
                make_float4(acc[i][0], acc[i][1], acc[i][2], acc[i][3]);
    }
}

// ---------------- per-node attention scalars: a_src[n,4], a_dst[n,4] ----------------
__global__ void att_kernel(const float* __restrict__ att_s, const float* __restrict__ att_d,
                           int which, int n) {
    const float* h = which ? g_h2 : g_h1;
    float* as_ = which ? g_asrc2 : g_asrc1;
    float* ad_ = which ? g_adst2 : g_adst1;
    int gid = blockIdx.x * blockDim.x + threadIdx.x;
    int w = gid >> 5, lane = threadIdx.x & 31;
    if (w >= n) return;
    float4 hv = *(const float4*)(h + w*128 + lane*4);
    float4 sv = *(const float4*)(att_s + lane*4);
    float4 dv = *(const float4*)(att_d + lane*4);
    float ps = hv.x*sv.x + hv.y*sv.y + hv.z*sv.z + hv.w*sv.w;
    float pd = hv.x*dv.x + hv.y*dv.y + hv.z*dv.z + hv.w*dv.w;
    #pragma unroll
    for (int off = 4; off >= 1; off >>= 1) {
        ps += __shfl_down_sync(0xffffffffu, ps, off);
        pd += __shfl_down_sync(0xffffffffu, pd, off);
    }
    if ((lane & 7) == 0) {
        as_[w*4 + (lane >> 3)] = ps;
        ad_[w*4 + (lane >> 3)] = pd;
    }
}

// ---------------- edge pass 1: segment max ----------------
__global__ void edge_max_kernel(const int* __restrict__ src, const int* __restrict__ dst,
                                int which, int Ereal, int n) {
    const float* as_ = which ? g_asrc2 : g_asrc1;
    const float* ad_ = which ? g_adst2 : g_adst1;
    float* m = which ? g_m2 : g_m1;
    int e = blockIdx.x * blockDim.x + threadIdx.x;
    if (e >= Ereal + n) return;
    int si, di;
    if (e < Ereal) { si = src[e]; di = dst[e]; } else { si = di = e - Ereal; }
    float4 a = *(const float4*)(as_ + si*4);
    float4 b = *(const float4*)(ad_ + di*4);
    float v0 = a.x + b.x; v0 = v0 > 0.f ? v0 : 0.2f*v0;
    float v1 = a.y + b.y; v1 = v1 > 0.f ? v1 : 0.2f*v1;
    float v2 = a.z + b.z; v2 = v2 > 0.f ? v2 : 0.2f*v2;
    float v3 = a.w + b.w; v3 = v3 > 0.f ? v3 : 0.2f*v3;
    atomicMaxF(&m[di*4 + 0], v0);
    atomicMaxF(&m[di*4 + 1], v1);
    atomicMaxF(&m[di*4 + 2], v2);
    atomicMaxF(&m[di*4 + 3], v3);
}

// ---------------- edge pass 2: sum of exp ----------------
__global__ void edge_sum_kernel(const int* __restrict__ src, const int* __restrict__ dst,
                                int which, int Ereal, int n) {
    const float* as_ = which ? g_asrc2 : g_asrc1;
    const float* ad_ = which ? g_adst2 : g_adst1;
    const float* m = which ? g_m2 : g_m1;
    float* s = which ? g_s2 : g_s1;
    int e = blockIdx.x * blockDim.x + threadIdx.x;
    if (e >= Ereal + n) return;
    int si, di;
    if (e < Ereal) { si = src[e]; di = dst[e]; } else { si = di = e - Ereal; }
    float4 a  = *(const float4*)(as_ + si*4);
    float4 b  = *(const float4*)(ad_ + di*4);
    float4 mv = *(const float4*)(m + di*4);
    float v0 = a.x + b.x; v0 = v0 > 0.f ? v0 : 0.2f*v0;
    float v1 = a.y + b.y; v1 = v1 > 0.f ? v1 : 0.2f*v1;
    float v2 = a.z + b.z; v2 = v2 > 0.f ? v2 : 0.2f*v2;
    float v3 = a.w + b.w; v3 = v3 > 0.f ? v3 : 0.2f*v3;
    atomicAdd(&s[di*4 + 0], expf(v0 - mv.x));
    atomicAdd(&s[di*4 + 1], expf(v1 - mv.y));
    atomicAdd(&s[di*4 + 2], expf(v2 - mv.z));
    atomicAdd(&s[di*4 + 3], expf(v3 - mv.w));
}

// ---------------- edge pass 3: alpha-weighted aggregation (warp per edge) ----------------
__global__ void edge_agg_kernel(const int* __restrict__ src, const int* __restrict__ dst,
                                int which, int Ereal, int n) {
    const float* as_ = which ? g_asrc2 : g_asrc1;
    const float* ad_ = which ? g_adst2 : g_adst1;
    const float* m  = which ? g_m2 : g_m1;
    const float* sm = which ? g_s2 : g_s1;
    const float* h  = which ? g_h2 : g_h1;
    float* out = which ? g_xg : g_xout;
    int gid = blockIdx.x * blockDim.x + threadIdx.x;
    int w = gid >> 5, lane = threadIdx.x & 31;
    if (w >= Ereal + n) return;
    int si, di;
    if (w < Ereal) { si = src[w]; di = dst[w]; } else { si = di = w - Ereal; }
    int hd = lane >> 3;
    float e = as_[si*4 + hd] + ad_[di*4 + hd];
    e = e > 0.f ? e : 0.2f*e;
    float alpha = expf(e - m[di*4 + hd]) / (sm[di*4 + hd] + 1e-16f);
    float4 hv = *(const float4*)(h + si*128 + lane*4);
    float* o = out + di*128 + lane*4;
    atomicAdd(o + 0, alpha * hv.x);
    atomicAdd(o + 1, alpha * hv.y);
    atomicAdd(o + 2, alpha * hv.z);
    atomicAdd(o + 3, alpha * hv.w);
}

// ---------------- x_g_out = g_xg + bias2; also write to d_out tail ----------------
__global__ void finalize2_kernel(const float* __restrict__ bias2, float* __restrict__ dtail) {
    int i = blockIdx.x * blockDim.x + threadIdx.x;
    if (i >= Gg*128) return;
    float v = g_xg[i] + bias2[i & 127];
    g_xgf[i] = v;
    dtail[i] = v;
}

// ---------------- adjacency mean over group edges ----------------
__global__ void adj_accum_kernel(const int* __restrict__ eg) {
    int gid = blockIdx.x * blockDim.x + threadIdx.x;
    int w = gid >> 5, lane = threadIdx.x & 31;
    if (w >= EGe) return;
    int a = eg[w];         // edge_index_g[0]
    int b = eg[EGe + w];   // edge_index_g[1]
    float4 v = *(const float4*)(g_xgf + b*128 + lane*4);
    float* o = g_adj + a*128 + lane*4;
    atomicAdd(o + 0, v.x);
    atomicAdd(o + 1, v.y);
    atomicAdd(o + 2, v.z);
    atomicAdd(o + 3, v.w);
    if (lane == 0) atomicAdd(&g_cnt[a], 1.f);
}

__global__ void adj_mean_kernel() {
    int i = blockIdx.x * blockDim.x + threadIdx.x;
    if (i < Gg*128) g_adj[i] = g_adj[i] / fmaxf(g_cnt[i >> 7], 1.f);
}

// ---------------- final: bilinear update + FC 128->32 (warp per node) ----------------
__global__ void final_kernel(const float* __restrict__ bias1, const int* __restrict__ node_group,
                             const float* __restrict__ Wfc, const float* __restrict__ bfc,
                             float* __restrict__ out) {
    __shared__ float Ws[128*32];
    __shared__ float Us[8][128];
    int t = threadIdx.x;
    for (int i = t; i < 128*32; i += 256) Ws[i] = Wfc[i];
    __syncthreads();
    int w = t >> 5, lane = t & 31;
    float4 b1 = *(const float4*)(bias1 + lane*4);
    float bf = bfc[lane];
    for (int j = 0; j < 4; j++) {
        int node = blockIdx.x*32 + w*4 + j;
        if (node < Nn) {
            float4 xo = *(const float4*)(g_xout + node*128 + lane*4);
            xo.x += b1.x; xo.y += b1.y; xo.z += b1.z; xo.w += b1.w;
            int g = node_group[node];
            float4 gf = *(const float4*)(g_xgf + g*128 + lane*4);
            float4 af = *(const float4*)(g_adj + g*128 + lane*4);
            float pg = xo.x*gf.x + xo.y*gf.y + xo.z*gf.z + xo.w*gf.w;
            float pa = xo.x*af.x + xo.y*af.y + xo.z*af.z + xo.w*af.w;
            #pragma unroll
            for (int off = 16; off >= 1; off >>= 1) {
                pg += __shfl_xor_sync(0xffffffffu, pg, off);
                pa += __shfl_xor_sync(0xffffffffu, pa, off);
            }
            float4 u;
            u.x = xo.x + pg*gf.x + pa*af.x;
            u.y = xo.y + pg*gf.y + pa*af.y;
            u.z = xo.z + pg*gf.z + pa*af.z;
            u.w = xo.w + pg*gf.w + pa*af.w;
            *(float4*)&Us[w][lane*4] = u;
            __syncwarp();
            float acc = bf;
            #pragma unroll
            for (int k = 0; k < 128; k++) acc += Us[w][k] * Ws[k*32 + lane];
            out[node*32 + lane] = acc;
            __syncwarp();
        }
    }
}

// ---------------- launch ----------------
extern "C" void kernel_launch(void* const* d_in, const int* in_sizes, int n_in,
                              void* d_out, int out_size) {
    const float* x    = (const float*)d_in[0];
    const float* x_g  = (const float*)d_in[1];
    const int*   ei   = (const int*)d_in[2];
    const int*   eig  = (const int*)d_in[3];
    const int*   ngrp = (const int*)d_in[4];
    const float* W1   = (const float*)d_in[5];
    const float* as1  = (const float*)d_in[6];
    const float* ad1  = (const float*)d_in[7];
    const float* b1   = (const float*)d_in[8];
    const float* W2   = (const float*)d_in[9];
    const float* as2  = (const float*)d_in[10];
    const float* ad2  = (const float*)d_in[11];
    const float* b2   = (const float*)d_in[12];
    const float* Wfc  = (const float*)d_in[13];
    const float* bfc  = (const float*)d_in[14];
    float* out = (float*)d_out;

    init_kernel<<<(Nn*128 + 255)/256, 256>>>();

    gemm_k128<<<(Nn + 63)/64, 256>>>(x,   W1, 0, Nn);
    gemm_k128<<<(Gg + 63)/64, 256>>>(x_g, W2, 1, Gg);

    att_kernel<<<(Nn*32 + 255)/256, 256>>>(as1, ad1, 0, Nn);
    att_kernel<<<(Gg*32 + 255)/256, 256>>>(as2, ad2, 1, Gg);

    edge_max_kernel<<<(Ee + Nn + 255)/256, 256>>>(ei,  ei + Ee,   0, Ee,  Nn);
    edge_max_kernel<<<(EGe + Gg + 255)/256, 256>>>(eig, eig + EGe, 1, EGe, Gg);

    edge_sum_kernel<<<(Ee + Nn + 255)/256, 256>>>(ei,  ei + Ee,   0, Ee,  Nn);
    edge_sum_kernel<<<(EGe + Gg + 255)/256, 256>>>(eig, eig + EGe, 1, EGe, Gg);

    edge_agg_kernel<<<((Ee + Nn)*32 + 255)/256, 256>>>(ei,  ei + Ee,   0, Ee,  Nn);
    edge_agg_kernel<<<((EGe + Gg)*32 + 255)/256, 256>>>(eig, eig + EGe, 1, EGe, Gg);

    finalize2_kernel<<<(Gg*128 + 255)/256, 256>>>(b2, out + Nn*32);
    adj_accum_kernel<<<(EGe*32 + 255)/256, 256>>>(eig);
    adj_mean_kernel<<<(Gg*128 + 255)/256, 256>>>();

    final_kernel<<<(Nn + 31)/32, 256>>>(b1, ngrp, Wfc, bfc, out);
}

// round 2
// speedup vs baseline: 1.5926x; 1.5926x over previous
#include <cuda_runtime.h>

#define Nn 100000
#define Gg 1000
#define Ee 1600000
#define EGe 16000

// ---------------- scratch (device globals; no runtime allocation) ----------------
static __device__ __align__(16) float g_h1[Nn*128];     // x @ W1
static __device__ __align__(16) float g_xout[Nn*128];   // GAT1 aggregation
static __device__ __align__(16) float g_asrc1[Nn*4];
static __device__ __align__(16) float g_adst1[Nn*4];
static __device__ __align__(16) float g_s1[Nn*4];
static __device__ __align__(16) float g_h2[Gg*128];
static __device__ __align__(16) float g_xg[Gg*128];     // GAT2 aggregation (pre-bias)
static __device__ __align__(16) float g_xgf[Gg*128];    // GAT2 final (with bias2)
static __device__ __align__(16) float g_adj[Gg*128];    // adjacent-group mean
static __device__ __align__(16) float g_asrc2[Gg*4];
static __device__ __align__(16) float g_adst2[Gg*4];
static __device__ __align__(16) float g_s2[Gg*4];
static __device__ float g_cnt[Gg];

__device__ __forceinline__ void redAddV4(float* p, float a, float b, float c, float d) {
    asm volatile("red.global.add.v4.f32 [%0], {%1, %2, %3, %4};"
                 :: "l"(p), "f"(a), "f"(b), "f"(c), "f"(d) : "memory");
}

// ---------------- init ----------------
__global__ void init_kernel() {
    int i = blockIdx.x * blockDim.x + threadIdx.x;
    if (i < Nn*128) g_xout[i] = 0.f;
    if (i < Nn*4) g_s1[i] = 0.f;
    if (i < Gg*128) { g_xg[i] = 0.f; g_adj[i] = 0.f; }
    if (i < Gg*4) g_s2[i] = 0.f;
    if (i < Gg) g_cnt[i] = 0.f;
}

// ---------------- GEMM: C[n,128] = A[n,128] @ B[128,128], fused attention scores ----
// 256 threads, tile 64 rows x 128 cols, K-chunks of 16, 8x4 microtile/thread.
// Each warp (tr) owns 8 full rows spread across 32 lanes (tc = 4 cols each), so
// the per-head attention dots reduce within aligned 8-lane groups.
__global__ void gemm_k128(const float* __restrict__ A, const float* __restrict__ B,
                          const float* __restrict__ att_s, const float* __restrict__ att_d,
                          int which, int n) {
    float* C   = which ? g_h2 : g_h1;
    float* as_ = which ? g_asrc2 : g_asrc1;
    float* ad_ = which ? g_adst2 : g_adst1;
    __shared__ float As[16][68];   // [k][row], padded
    __shared__ float Bs[16][128];  // [k][col]
    int t = threadIdx.x;
    int rowBase = blockIdx.x * 64;
    int tr = t >> 5, tc = t & 31;
    float acc[8][4];
    #pragma unroll
    for (int i = 0; i < 8; i++)
        #pragma unroll
        for (int j = 0; j < 4; j++) acc[i][j] = 0.f;

    for (int kt = 0; kt < 128; kt += 16) {
        int ar = t >> 2;
        int ac = (t & 3) << 2;
        int row = rowBase + ar;
        float4 av = (row < n) ? *(const float4*)(A + row*128 + kt + ac)
                              : make_float4(0.f, 0.f, 0.f, 0.f);
        As[ac+0][ar] = av.x; As[ac+1][ar] = av.y;
        As[ac+2][ar] = av.z; As[ac+3][ar] = av.w;
        int br = t >> 4;
        int bc = (t & 15) << 3;
        float4 b0 = *(const float4*)(B + (kt + br)*128 + bc);
        float4 b1 = *(const float4*)(B + (kt + br)*128 + bc + 4);
        *(float4*)&Bs[br][bc]     = b0;
        *(float4*)&Bs[br][bc + 4] = b1;
        __syncthreads();
        #pragma unroll
        for (int kk = 0; kk < 16; kk++) {
            float4 a0 = *(const float4*)&As[kk][tr*8];
            float4 a1 = *(const float4*)&As[kk][tr*8 + 4];
            float4 b  = *(const float4*)&Bs[kk][tc*4];
            float av_[8] = {a0.x,a0.y,a0.z,a0.w,a1.x,a1.y,a1.z,a1.w};
            #pragma unroll
            for (int i = 0; i < 8; i++) {
                acc[i][0] += av_[i]*b.x; acc[i][1] += av_[i]*b.y;
                acc[i][2] += av_[i]*b.z; acc[i][3] += av_[i]*b.w;
            }
        }
        __syncthreads();
    }
    float4 sa = *(const float4*)(att_s + tc*4);
    float4 da = *(const float4*)(att_d + tc*4);
    int head = tc >> 3;
    #pragma unroll
    for (int i = 0; i < 8; i++) {
        int row = rowBase + tr*8 + i;
        if (row < n) {
            *(float4*)(C + row*128 + tc*4) =
                make_float4(acc[i][0], acc[i][1], acc[i][2], acc[i][3]);
            float ps = acc[i][0]*sa.x + acc[i][1]*sa.y + acc[i][2]*sa.z + acc[i][3]*sa.w;
            float pd = acc[i][0]*da.x + acc[i][1]*da.y + acc[i][2]*da.z + acc[i][3]*da.w;
            #pragma unroll
            for (int off = 4; off >= 1; off >>= 1) {
                ps += __shfl_xor_sync(0xffffffffu, ps, off);
                pd += __shfl_xor_sync(0xffffffffu, pd, off);
            }
            if ((tc & 7) == 0) {
                as_[row*4 + head] = ps;
                ad_[row*4 + head] = pd;
            }
        }
    }
}

// ---------------- edge pass 1: sum of exp (no max shift; scores are O(1)) ------
__global__ void edge_sum_kernel(const int* __restrict__ src, const int* __restrict__ dst,
                                int which, int Ereal, int n) {
    const float* as_ = which ? g_asrc2 : g_asrc1;
    const float* ad_ = which ? g_adst2 : g_adst1;
    float* s = which ? g_s2 : g_s1;
    int e = blockIdx.x * blockDim.x + threadIdx.x;
    if (e >= Ereal + n) return;
    int si, di;
    if (e < Ereal) { si = src[e]; di = dst[e]; } else { si = di = e - Ereal; }
    float4 a  = *(const float4*)(as_ + si*4);
    float4 b  = *(const float4*)(ad_ + di*4);
    float v0 = a.x + b.x; v0 = v0 > 0.f ? v0 : 0.2f*v0;
    float v1 = a.y + b.y; v1 = v1 > 0.f ? v1 : 0.2f*v1;
    float v2 = a.z + b.z; v2 = v2 > 0.f ? v2 : 0.2f*v2;
    float v3 = a.w + b.w; v3 = v3 > 0.f ? v3 : 0.2f*v3;
    redAddV4(&s[di*4], __expf(v0), __expf(v1), __expf(v2), __expf(v3));
}

// ---------------- edge pass 2: alpha-weighted aggregation (warp per edge) ------
__global__ void edge_agg_kernel(const int* __restrict__ src, const int* __restrict__ dst,
                                int which, int Ereal, int n) {
    const float* as_ = which ? g_asrc2 : g_asrc1;
    const float* ad_ = which ? g_adst2 : g_adst1;
    const float* sm = which ? g_s2 : g_s1;
    const float* h  = which ? g_h2 : g_h1;
    float* out = which ? g_xg : g_xout;
    int gid = blockIdx.x * blockDim.x + threadIdx.x;
    int w = gid >> 5, lane = threadIdx.x & 31;
    if (w >= Ereal + n) return;
    int si, di;
    if (w < Ereal) { si = src[w]; di = dst[w]; } else { si = di = w - Ereal; }
    int hd = lane >> 3;
    float e = __ldg(&as_[si*4 + hd]) + __ldg(&ad_[di*4 + hd]);
    e = e > 0.f ? e : 0.2f*e;
    float alpha = __expf(e) / (__ldg(&sm[di*4 + hd]) + 1e-16f);
    float4 hv = *(const float4*)(h + si*128 + lane*4);
    redAddV4(out + di*128 + lane*4, alpha*hv.x, alpha*hv.y, alpha*hv.z, alpha*hv.w);
}

// ---------------- x_g_out = g_xg + bias2; also write to d_out tail ----------------
__global__ void finalize2_kernel(const float* __restrict__ bias2, float* __restrict__ dtail) {
    int i = blockIdx.x * blockDim.x + threadIdx.x;
    if (i >= Gg*128) return;
    float v = g_xg[i] + bias2[i & 127];
    g_xgf[i] = v;
    dtail[i] = v;
}

// ---------------- adjacency mean over group edges ----------------
__global__ void adj_accum_kernel(const int* __restrict__ eg) {
    int gid = blockIdx.x * blockDim.x + threadIdx.x;
    int w = gid >> 5, lane = threadIdx.x & 31;
    if (w >= EGe) return;
    int a = eg[w];         // edge_index_g[0]
    int b = eg[EGe + w];   // edge_index_g[1]
    float4 v = *(const float4*)(g_xgf + b*128 + lane*4);
    redAddV4(g_adj + a*128 + lane*4, v.x, v.y, v.z, v.w);
    if (lane == 0) atomicAdd(&g_cnt[a], 1.f);
}

__global__ void adj_mean_kernel() {
    int i = blockIdx.x * blockDim.x + threadIdx.x;
    if (i < Gg*128) g_adj[i] = g_adj[i] / fmaxf(g_cnt[i >> 7], 1.f);
}

// ---------------- final: bilinear update + FC 128->32 (warp per node) ----------------
__global__ void final_kernel(const float* __restrict__ bias1, const int* __restrict__ node_group,
                             const float* __restrict__ Wfc, const float* __restrict__ bfc,
                             float* __restrict__ out) {
    __shared__ float Ws[128*32];
    __shared__ float Us[8][128];
    int t = threadIdx.x;
    for (int i = t; i < 128*32; i += 256) Ws[i] = Wfc[i];
    __syncthreads();
    int w = t >> 5, lane = t & 31;
    float4 b1 = *(const float4*)(bias1 + lane*4);
    float bf = bfc[lane];
    for (int j = 0; j < 4; j++) {
        int node = blockIdx.x*32 + w*4 + j;
        if (node < Nn) {
            float4 xo = *(const float4*)(g_xout + node*128 + lane*4);
            xo.x += b1.x; xo.y += b1.y; xo.z += b1.z; xo.w += b1.w;
            int g = node_group[node];
            float4 gf = *(const float4*)(g_xgf + g*128 + lane*4);
            float4 af = *(const float4*)(g_adj + g*128 + lane*4);
            float pg = xo.x*gf.x + xo.y*gf.y + xo.z*gf.z + xo.w*gf.w;
            float pa = xo.x*af.x + xo.y*af.y + xo.z*af.z + xo.w*af.w;
            #pragma unroll
            for (int off = 16; off >= 1; off >>= 1) {
                pg += __shfl_xor_sync(0xffffffffu, pg, off);
                pa += __shfl_xor_sync(0xffffffffu, pa, off);
            }
            float4 u;
            u.x = xo.x + pg*gf.x + pa*af.x;
            u.y = xo.y + pg*gf.y + pa*af.y;
            u.z = xo.z + pg*gf.z + pa*af.z;
            u.w = xo.w + pg*gf.w + pa*af.w;
            *(float4*)&Us[w][lane*4] = u;
            __syncwarp();
            float acc = bf;
            #pragma unroll
            for (int k = 0; k < 128; k++) acc += Us[w][k] * Ws[k*32 + lane];
            out[node*32 + lane] = acc;
            __syncwarp();
        }
    }
}

// ---------------- launch ----------------
extern "C" void kernel_launch(void* const* d_in, const int* in_sizes, int n_in,
                              void* d_out, int out_size) {
    const float* x    = (const float*)d_in[0];
    const float* x_g  = (const float*)d_in[1];
    const int*   ei   = (const int*)d_in[2];
    const int*   eig  = (const int*)d_in[3];
    const int*   ngrp = (const int*)d_in[4];
    const float* W1   = (const float*)d_in[5];
    const float* as1  = (const float*)d_in[6];
    const float* ad1  = (const float*)d_in[7];
    const float* b1   = (const float*)d_in[8];
    const float* W2   = (const float*)d_in[9];
    const float* as2  = (const float*)d_in[10];
    const float* ad2  = (const float*)d_in[11];
    const float* b2   = (const float*)d_in[12];
    const float* Wfc  = (const float*)d_in[13];
    const float* bfc  = (const float*)d_in[14];
    float* out = (float*)d_out;

    init_kernel<<<(Nn*128 + 255)/256, 256>>>();

    gemm_k128<<<(Nn + 63)/64, 256>>>(x,   W1, as1, ad1, 0, Nn);
    gemm_k128<<<(Gg + 63)/64, 256>>>(x_g, W2, as2, ad2, 1, Gg);

    edge_sum_kernel<<<(Ee + Nn + 255)/256, 256>>>(ei,  ei + Ee,   0, Ee,  Nn);
    edge_sum_kernel<<<(EGe + Gg + 255)/256, 256>>>(eig, eig + EGe, 1, EGe, Gg);

    edge_agg_kernel<<<((Ee + Nn)*32 + 255)/256, 256>>>(ei,  ei + Ee,   0, Ee,  Nn);
    edge_agg_kernel<<<((EGe + Gg)*32 + 255)/256, 256>>>(eig, eig + EGe, 1, EGe, Gg);

    finalize2_kernel<<<(Gg*128 + 255)/256, 256>>>(b2, out + Nn*32);
    adj_accum_kernel<<<(EGe*32 + 255)/256, 256>>>(eig);
    adj_mean_kernel<<<(Gg*128 + 255)/256, 256>>>();

    final_kernel<<<(Nn + 31)/32, 256>>>(b1, ngrp, Wfc, bfc, out);
}

// round 4
// speedup vs baseline: 2.4371x; 1.5303x over previous
#include <cuda_runtime.h>

#define Nn 100000
#define Gg 1000
#define Ee 1600000
#define EGe 16000
#define SCAN_BS 512
#define NB1 ((Nn + SCAN_BS - 1) / SCAN_BS)
#define NB2 ((Gg + SCAN_BS - 1) / SCAN_BS)

// ---------------- scratch (device globals; no runtime allocation) ----------------
static __device__ __align__(16) float g_h1[Nn*128];     // x @ W1
static __device__ __align__(16) float g_xout[Nn*128];   // GAT1 aggregation (pre-bias)
static __device__ __align__(16) float g_asrc1[Nn*4];
static __device__ __align__(16) float g_adst1[Nn*4];
static __device__ __align__(16) float g_h2[Gg*128];
static __device__ __align__(16) float g_xg[Gg*128];     // GAT2 aggregation (pre-bias)
static __device__ __align__(16) float g_xgf[Gg*128];    // GAT2 final (with bias2)
static __device__ __align__(16) float g_adj[Gg*128];    // adjacent-group mean
static __device__ __align__(16) float g_asrc2[Gg*4];
static __device__ __align__(16) float g_adst2[Gg*4];
static __device__ float g_cnt[Gg];

// CSR scratch
static __device__ int g_deg1[Nn];
static __device__ int g_row1[Nn + 1];
static __device__ int g_cur1[Nn];
static __device__ int g_csr1[Ee + Nn];
static __device__ int g_bsum1[NB1];
static __device__ int g_deg2[Gg];
static __device__ int g_row2[Gg + 1];
static __device__ int g_cur2[Gg];
static __device__ int g_csr2[EGe + Gg];
static __device__ int g_bsum2[NB2];

__device__ __forceinline__ void redAddV4(float* p, float a, float b, float c, float d) {
    asm volatile("red.global.add.v4.f32 [%0], {%1, %2, %3, %4};"
                 :: "l"(p), "f"(a), "f"(b), "f"(c), "f"(d) : "memory");
}

// ---------------- init: MUST cover max(Nn, Gg*128) = 128000 threads ----------------
__global__ void init_kernel() {
    int i = blockIdx.x * blockDim.x + threadIdx.x;
    if (i < Nn) g_deg1[i] = 1;            // self-loop baked into degree
    if (i < Gg*128) g_adj[i] = 0.f;       // 128000 elements — full coverage critical
    if (i < Gg) { g_deg2[i] = 1; g_cnt[i] = 0.f; }
}

// ---------------- histogram of dst ----------------
__global__ void hist_kernel(const int* __restrict__ dst, int* __restrict__ deg, int Ereal) {
    int e = blockIdx.x * blockDim.x + threadIdx.x;
    if (e < Ereal) atomicAdd(&deg[dst[e]], 1);
}

// ---------------- 3-phase exclusive scan ----------------
__global__ void scan1_kernel(const int* __restrict__ deg, int n,
                             int* __restrict__ row, int* __restrict__ bsum) {
    __shared__ int s[SCAN_BS];
    int tid = threadIdx.x;
    int i = blockIdx.x * SCAN_BS + tid;
    int v = (i < n) ? deg[i] : 0;
    s[tid] = v;
    __syncthreads();
    #pragma unroll
    for (int off = 1; off < SCAN_BS; off <<= 1) {
        int t = (tid >= off) ? s[tid - off] : 0;
        __syncthreads();
        s[tid] += t;
        __syncthreads();
    }
    if (i < n) row[i] = s[tid] - v;   // exclusive
    if (tid == SCAN_BS - 1) bsum[blockIdx.x] = s[tid];
}

__global__ void scan2_kernel(int* __restrict__ bsum, int nb) {
    __shared__ int s[256];
    int tid = threadIdx.x;
    int v = (tid < nb) ? bsum[tid] : 0;
    s[tid] = v;
    __syncthreads();
    #pragma unroll
    for (int off = 1; off < 256; off <<= 1) {
        int t = (tid >= off) ? s[tid - off] : 0;
        __syncthreads();
        s[tid] += t;
        __syncthreads();
    }
    if (tid < nb) bsum[tid] = s[tid] - v;  // exclusive
}

__global__ void scan3_kernel(int* __restrict__ row, const int* __restrict__ bsum,
                             int* __restrict__ cur, int n, int total) {
    int i = blockIdx.x * SCAN_BS + threadIdx.x;
    if (i < n) {
        int r = row[i] + bsum[blockIdx.x];
        row[i] = r;
        cur[i] = r;
    }
    if (i == 0) row[n] = total;
}

// ---------------- scatter edges (+self-loops) into CSR by dst ----------------
__global__ void scatter_kernel(const int* __restrict__ src, const int* __restrict__ dst,
                               int* __restrict__ cur, int* __restrict__ csr,
                               int Ereal, int n) {
    int e = blockIdx.x * blockDim.x + threadIdx.x;
    if (e >= Ereal + n) return;
    int si, di;
    if (e < Ereal) { si = src[e]; di = dst[e]; } else { si = di = e - Ereal; }
    int pos = atomicAdd(&cur[di], 1);
    csr[pos] = si;
}

// ---------------- fused softmax + aggregation: warp per dst node ----------------
// out[d] = sum_e exp(leaky(a_src[s]+a_dst[d])) * h[s] / sum_e exp(...)
__global__ void csr_agg_kernel(int which, int n) {
    const float* as_ = which ? g_asrc2 : g_asrc1;
    const float* ad_ = which ? g_adst2 : g_adst1;
    const float* h   = which ? g_h2 : g_h1;
    const int* row   = which ? g_row2 : g_row1;
    const int* csr   = which ? g_csr2 : g_csr1;
    float* out       = which ? g_xg : g_xout;
    int gid = blockIdx.x * blockDim.x + threadIdx.x;
    int d = gid >> 5, lane = threadIdx.x & 31;
    if (d >= n) return;
    int start = row[d], end = row[d + 1];
    int hd = lane >> 3;
    float adv = __ldg(&ad_[d*4 + hd]);
    float4 acc = make_float4(0.f, 0.f, 0.f, 0.f);
    float wsum = 0.f;
    int si = __ldg(&csr[start]);               // prefetch first index
    for (int j = start; j < end; j++) {
        int sn = (j + 1 < end) ? __ldg(&csr[j + 1]) : 0;
        float a = __ldg(&as_[si*4 + hd]);
        float4 hv = *(const float4*)(h + si*128 + lane*4);
        float e = a + adv;
        e = e > 0.f ? e : 0.2f*e;
        float w = __expf(e);
        acc.x += w*hv.x; acc.y += w*hv.y; acc.z += w*hv.z; acc.w += w*hv.w;
        wsum += w;
        si = sn;
    }
    float inv = 1.f / (wsum + 1e-16f);
    *(float4*)(out + d*128 + lane*4) =
        make_float4(acc.x*inv, acc.y*inv, acc.z*inv, acc.w*inv);
}

// ---------------- GEMM: C[n,128] = A[n,128] @ B[128,128], fused attention scores ----
__global__ void gemm_k128(const float* __restrict__ A, const float* __restrict__ B,
                          const float* __restrict__ att_s, const float* __restrict__ att_d,
                          int which, int n) {
    float* C   = which ? g_h2 : g_h1;
    float* as_ = which ? g_asrc2 : g_asrc1;
    float* ad_ = which ? g_adst2 : g_adst1;
    __shared__ float As[16][68];   // [k][row], padded
    __shared__ float Bs[16][128];  // [k][col]
    int t = threadIdx.x;
    int rowBase = blockIdx.x * 64;
    int tr = t >> 5, tc = t & 31;
    float acc[8][4];
    #pragma unroll
    for (int i = 0; i < 8; i++)
        #pragma unroll
        for (int j = 0; j < 4; j++) acc[i][j] = 0.f;

    for (int kt = 0; kt < 128; kt += 16) {
        int ar = t >> 2;
        int ac = (t & 3) << 2;
        int row = rowBase + ar;
        float4 av = (row < n) ? *(const float4*)(A + row*128 + kt + ac)
                              : make_float4(0.f, 0.f, 0.f, 0.f);
        As[ac+0][ar] = av.x; As[ac+1][ar] = av.y;
        As[ac+2][ar] = av.z; As[ac+3][ar] = av.w;
        int br = t >> 4;
        int bc = (t & 15) << 3;
        float4 b0 = *(const float4*)(B + (kt + br)*128 + bc);
        float4 b1 = *(const float4*)(B + (kt + br)*128 + bc + 4);
        *(float4*)&Bs[br][bc]     = b0;
        *(float4*)&Bs[br][bc + 4] = b1;
        __syncthreads();
        #pragma unroll
        for (int kk = 0; kk < 16; kk++) {
            float4 a0 = *(const float4*)&As[kk][tr*8];
            float4 a1 = *(const float4*)&As[kk][tr*8 + 4];
            float4 b  = *(const float4*)&Bs[kk][tc*4];
            float av_[8] = {a0.x,a0.y,a0.z,a0.w,a1.x,a1.y,a1.z,a1.w};
            #pragma unroll
            for (int i = 0; i < 8; i++) {
                acc[i][0] += av_[i]*b.x; acc[i][1] += av_[i]*b.y;
                acc[i][2] += av_[i]*b.z; acc[i][3] += av_[i]*b.w;
            }
        }
        __syncthreads();
    }
    float4 sa = *(const float4*)(att_s + tc*4);
    float4 da = *(const float4*)(att_d + tc*4);
    int head = tc >> 3;
    #pragma unroll
    for (int i = 0; i < 8; i++) {
        int row = rowBase + tr*8 + i;
        if (row < n) {
            *(float4*)(C + row*128 + tc*4) =
                make_float4(acc[i][0], acc[i][1], acc[i][2], acc[i][3]);
            float ps = acc[i][0]*sa.x + acc[i][1]*sa.y + acc[i][2]*sa.z + acc[i][3]*sa.w;
            float pd = acc[i][0]*da.x + acc[i][1]*da.y + acc[i][2]*da.z + acc[i][3]*da.w;
            #pragma unroll
            for (int off = 4; off >= 1; off >>= 1) {
                ps += __shfl_xor_sync(0xffffffffu, ps, off);
                pd += __shfl_xor_sync(0xffffffffu, pd, off);
            }
            if ((tc & 7) == 0) {
                as_[row*4 + head] = ps;
                ad_[row*4 + head] = pd;
            }
        }
    }
}

// ---------------- x_g_out = g_xg + bias2; also write to d_out tail ----------------
__global__ void finalize2_kernel(const float* __restrict__ bias2, float* __restrict__ dtail) {
    int i = blockIdx.x * blockDim.x + threadIdx.x;
    if (i >= Gg*128) return;
    float v = g_xg[i] + bias2[i & 127];
    g_xgf[i] = v;
    dtail[i] = v;
}

// ---------------- adjacency mean over group edges ----------------
__global__ void adj_accum_kernel(const int* __restrict__ eg) {
    int gid = blockIdx.x * blockDim.x + threadIdx.x;
    int w = gid >> 5, lane = threadIdx.x & 31;
    if (w >= EGe) return;
    int a = eg[w];         // edge_index_g[0]
    int b = eg[EGe + w];   // edge_index_g[1]
    float4 v = *(const float4*)(g_xgf + b*128 + lane*4);
    redAddV4(g_adj + a*128 + lane*4, v.x, v.y, v.z, v.w);
    if (lane == 0) atomicAdd(&g_cnt[a], 1.f);
}

__global__ void adj_mean_kernel() {
    int i = blockIdx.x * blockDim.x + threadIdx.x;
    if (i < Gg*128) g_adj[i] = g_adj[i] / fmaxf(g_cnt[i >> 7], 1.f);
}

// ---------------- final: bilinear update + FC 128->32 (warp per node) ----------------
__global__ void final_kernel(const float* __restrict__ bias1, const int* __restrict__ node_group,
                             const float* __restrict__ Wfc, const float* __restrict__ bfc,
                             float* __restrict__ out) {
    __shared__ float Ws[128*32];
    __shared__ float Us[8][128];
    int t = threadIdx.x;
    for (int i = t; i < 128*32; i += 256) Ws[i] = Wfc[i];
    __syncthreads();
    int w = t >> 5, lane = t & 31;
    float4 b1 = *(const float4*)(bias1 + lane*4);
    float bf = bfc[lane];
    for (int j = 0; j < 4; j++) {
        int node = blockIdx.x*32 + w*4 + j;
        if (node < Nn) {
            float4 xo = *(const float4*)(g_xout + node*128 + lane*4);
            xo.x += b1.x; xo.y += b1.y; xo.z += b1.z; xo.w += b1.w;
            int g = node_group[node];
            float4 gf = *(const float4*)(g_xgf + g*128 + lane*4);
            float4 af = *(const float4*)(g_adj + g*128 + lane*4);
            float pg = xo.x*gf.x + xo.y*gf.y + xo.z*gf.z + xo.w*gf.w;
            float pa = xo.x*af.x + xo.y*af.y + xo.z*af.z + xo.w*af.w;
            #pragma unroll
            for (int off = 16; off >= 1; off >>= 1) {
                pg += __shfl_xor_sync(0xffffffffu, pg, off);
                pa += __shfl_xor_sync(0xffffffffu, pa, off);
            }
            float4 u;
            u.x = xo.x + pg*gf.x + pa*af.x;
            u.y = xo.y + pg*gf.y + pa*af.y;
            u.z = xo.z + pg*gf.z + pa*af.z;
            u.w = xo.w + pg*gf.w + pa*af.w;
            *(float4*)&Us[w][lane*4] = u;
            __syncwarp();
            float acc = bf;
            #pragma unroll
            for (int k = 0; k < 128; k++) acc += Us[w][k] * Ws[k*32 + lane];
            out[node*32 + lane] = acc;
            __syncwarp();
        }
    }
}

// ---------------- launch ----------------
extern "C" void kernel_launch(void* const* d_in, const int* in_sizes, int n_in,
                              void* d_out, int out_size) {
    const float* x    = (const float*)d_in[0];
    const float* x_g  = (const float*)d_in[1];
    const int*   ei   = (const int*)d_in[2];
    const int*   eig  = (const int*)d_in[3];
    const int*   ngrp = (const int*)d_in[4];
    const float* W1   = (const float*)d_in[5];
    const float* as1  = (const float*)d_in[6];
    const float* ad1  = (const float*)d_in[7];
    const float* b1   = (const float*)d_in[8];
    const float* W2   = (const float*)d_in[9];
    const float* as2  = (const float*)d_in[10];
    const float* ad2  = (const float*)d_in[11];
    const float* b2   = (const float*)d_in[12];
    const float* Wfc  = (const float*)d_in[13];
    const float* bfc  = (const float*)d_in[14];
    float* out = (float*)d_out;

    // resolve device-global addresses for the scan/scatter plumbing
    int *deg1, *row1, *cur1, *csr1, *bsum1;
    int *deg2, *row2, *cur2, *csr2, *bsum2;
    cudaGetSymbolAddress((void**)&deg1,  g_deg1);
    cudaGetSymbolAddress((void**)&row1,  g_row1);
    cudaGetSymbolAddress((void**)&cur1,  g_cur1);
    cudaGetSymbolAddress((void**)&csr1,  g_csr1);
    cudaGetSymbolAddress((void**)&bsum1, g_bsum1);
    cudaGetSymbolAddress((void**)&deg2,  g_deg2);
    cudaGetSymbolAddress((void**)&row2,  g_row2);
    cudaGetSymbolAddress((void**)&cur2,  g_cur2);
    cudaGetSymbolAddress((void**)&csr2,  g_csr2);
    cudaGetSymbolAddress((void**)&bsum2, g_bsum2);

    // init grid must cover Gg*128 = 128000 (> Nn) — replay-state reset
    init_kernel<<<(Gg*128 + 255)/256, 256>>>();

    // CSR build (graph 1)
    hist_kernel<<<(Ee + 255)/256, 256>>>(ei + Ee, deg1, Ee);
    scan1_kernel<<<NB1, SCAN_BS>>>(deg1, Nn, row1, bsum1);
    scan2_kernel<<<1, 256>>>(bsum1, NB1);
    scan3_kernel<<<NB1, SCAN_BS>>>(row1, bsum1, cur1, Nn, Ee + Nn);
    scatter_kernel<<<(Ee + Nn + 255)/256, 256>>>(ei, ei + Ee, cur1, csr1, Ee, Nn);

    // CSR build (graph 2)
    hist_kernel<<<(EGe + 255)/256, 256>>>(eig + EGe, deg2, EGe);
    scan1_kernel<<<NB2, SCAN_BS>>>(deg2, Gg, row2, bsum2);
    scan2_kernel<<<1, 256>>>(bsum2, NB2);
    scan3_kernel<<<NB2, SCAN_BS>>>(row2, bsum2, cur2, Gg, EGe + Gg);
    scatter_kernel<<<(EGe + Gg + 255)/256, 256>>>(eig, eig + EGe, cur2, csr2, EGe, Gg);

    // GEMMs with fused attention scores
    gemm_k128<<<(Nn + 63)/64, 256>>>(x,   W1, as1, ad1, 0, Nn);
    gemm_k128<<<(Gg + 63)/64, 256>>>(x_g, W2, as2, ad2, 1, Gg);

    // fused softmax + aggregation (atomic-free)
    csr_agg_kernel<<<(Nn*32 + 255)/256, 256>>>(0, Nn);
    csr_agg_kernel<<<(Gg*32 + 255)/256, 256>>>(1, Gg);

    finalize2_kernel<<<(Gg*128 + 255)/256, 256>>>(b2, out + Nn*32);
    adj_accum_kernel<<<(EGe*32 + 255)/256, 256>>>(eig);
    adj_mean_kernel<<<(Gg*128 + 255)/256, 256>>>();

    final_kernel<<<(Nn + 31)/32, 256>>>(b1, ngrp, Wfc, bfc, out);
}